// round 2
// baseline (speedup 1.0000x reference)
#include <cuda_runtime.h>
#include <cstdint>

// Problem shapes (fixed for this registry entry)
#define BB   8
#define LC   16384
#define SSEQ 2048
#define HH   256
#define K2   512
#define MT   64          // rows per CTA
#define AS   516         // A smem stride (512 + 4 pad -> conflict-free frags)
#define WS   264         // W tile smem stride (256 + 8 pad -> conflict-free frags)
#define KT   32          // K tile
#define NKT  (K2 / KT)   // 16
#define NTH  256

__device__ __forceinline__ float to_tf32(float x) {
    uint32_t u;
    asm("cvt.rna.tf32.f32 %0, %1;" : "=r"(u) : "f"(x));
    return __uint_as_float(u);
}

__device__ __forceinline__ void mma_tf32(float d[4], const float a[4], const float b[2]) {
    asm volatile(
        "mma.sync.aligned.m16n8k8.row.col.f32.tf32.tf32.f32 "
        "{%0,%1,%2,%3}, {%4,%5,%6,%7}, {%8,%9}, {%0,%1,%2,%3};"
        : "+f"(d[0]), "+f"(d[1]), "+f"(d[2]), "+f"(d[3])
        : "r"(__float_as_uint(a[0])), "r"(__float_as_uint(a[1])),
          "r"(__float_as_uint(a[2])), "r"(__float_as_uint(a[3])),
          "r"(__float_as_uint(b[0])), "r"(__float_as_uint(b[1])));
}

__global__ __launch_bounds__(NTH, 1)
void syl_fused_kernel(const float* __restrict__ ce,
                      const void*  __restrict__ ta_raw,
                      const float* __restrict__ dh,
                      const float* __restrict__ W1, const float* __restrict__ b1,
                      const float* __restrict__ W2, const float* __restrict__ b2,
                      const float* __restrict__ gamma, const float* __restrict__ beta,
                      float* __restrict__ out)
{
    extern __shared__ float smem[];
    float* Asm = smem;                 // [MT][AS]  A = [char | tok/aligned] (tf32)
    float* Wt  = smem + MT * AS;       // [2][KT][WS] weight tiles (tf32)
    float* F   = Wt;                   // reused post-GEMM: [MT][WS] feats (fp32)
    __shared__ int s_is64;

    const int tid  = threadIdx.x;
    const int lane = tid & 31;
    const int wid  = tid >> 5;
    const int g    = lane >> 2;        // groupID
    const int tg   = lane & 3;         // thread-in-group
    const int wm   = wid & 1;          // warp M half (2 x 32 rows)
    const int wn   = wid >> 1;         // warp N quarter (4 x 64 cols)
    const int row0 = blockIdx.x * MT;

    // ---- dtype sniff for token_alignment (jax x64 off -> int32; on -> int64) ----
    if (tid == 0) {
        const int* t32 = (const int*)ta_raw;
        int ok = 1;
        #pragma unroll 1
        for (int k = 0; k < 64; k++) {
            int lo = t32[2 * k], hi = t32[2 * k + 1];
            if (!((hi == 0 && lo >= 0) || (hi == -1 && lo < 0))) { ok = 0; break; }
        }
        s_is64 = ok;
    }

    // ---- load char tile [MT x 256] -> Asm cols [0,256), cvt tf32 ----
    {
        const float4* ce4 = reinterpret_cast<const float4*>(ce + (size_t)row0 * HH);
        #pragma unroll
        for (int i = 0; i < (MT * HH / 4) / NTH; i++) {   // 16 float4 per thread
            int idx4 = tid + i * NTH;
            int r  = idx4 >> 6;
            int c4 = idx4 & 63;
            float4 v = ce4[idx4];
            float* dst = &Asm[r * AS + c4 * 4];
            dst[0] = to_tf32(v.x); dst[1] = to_tf32(v.y);
            dst[2] = to_tf32(v.z); dst[3] = to_tf32(v.w);
        }
    }
    __syncthreads();   // publish s_is64 (char stores don't conflict with gather region)
    const int is64 = s_is64;

    // ---- gather tok tile -> Asm cols [256,512), cvt tf32 ----
    {
        const long long* t64 = (const long long*)ta_raw;
        const int*       t32 = (const int*)ta_raw;
        #pragma unroll
        for (int rr = 0; rr < 8; rr++) {
            int r  = wid * 8 + rr;
            int gr = row0 + r;
            long long idx = is64 ? t64[gr] : (long long)t32[gr];
            float* dstrow = &Asm[r * AS + 256];
            if (idx < 0) {
                #pragma unroll
                for (int j = 0; j < 2; j++) {
                    int c4 = lane + j * 32;
                    float* dst = dstrow + c4 * 4;
                    dst[0] = 0.f; dst[1] = 0.f; dst[2] = 0.f; dst[3] = 0.f;
                }
            } else {
                int ii = (int)idx; if (ii > SSEQ - 1) ii = SSEQ - 1;
                int b = gr / LC;
                const float4* src = reinterpret_cast<const float4*>(dh + ((size_t)b * SSEQ + ii) * HH);
                #pragma unroll
                for (int j = 0; j < 2; j++) {
                    int c4 = lane + j * 32;
                    float4 v = src[c4];
                    float* dst = dstrow + c4 * 4;
                    dst[0] = to_tf32(v.x); dst[1] = to_tf32(v.y);
                    dst[2] = to_tf32(v.z); dst[3] = to_tf32(v.w);
                }
            }
        }
    }

    float acc[2][8][4];
    float4 wreg[8];

    // preload W1 tile 0 into registers
    {
        const float4* w4 = reinterpret_cast<const float4*>(W1);
        #pragma unroll
        for (int j = 0; j < 8; j++) wreg[j] = w4[tid + j * NTH];
    }

    const float* const Wg2[2] = { W1, W2 };

    #pragma unroll 1
    for (int gemm = 0; gemm < 2; gemm++) {
        #pragma unroll
        for (int mi = 0; mi < 2; mi++)
            #pragma unroll
            for (int ni = 0; ni < 8; ni++)
                #pragma unroll
                for (int c = 0; c < 4; c++) acc[mi][ni][c] = 0.f;

        #pragma unroll 1
        for (int kt = 0; kt < NKT; kt++) {
            float* wb = Wt + (kt & 1) * KT * WS;

            // commit staged W tile to smem (tf32)
            #pragma unroll
            for (int j = 0; j < 8; j++) {
                int idx4 = tid + j * NTH;
                int kk = idx4 >> 6;
                int c4 = idx4 & 63;
                float* dst = &wb[kk * WS + c4 * 4];
                dst[0] = to_tf32(wreg[j].x); dst[1] = to_tf32(wreg[j].y);
                dst[2] = to_tf32(wreg[j].z); dst[3] = to_tf32(wreg[j].w);
            }
            __syncthreads();

            // prefetch next W tile (overlaps with MMA below)
            {
                const float* nW = nullptr; int nkt = 0;
                if (kt < NKT - 1)      { nW = Wg2[gemm]; nkt = kt + 1; }
                else if (gemm == 0)    { nW = W2;        nkt = 0; }
                if (nW) {
                    const float4* w4 = reinterpret_cast<const float4*>(nW + nkt * KT * HH);
                    #pragma unroll
                    for (int j = 0; j < 8; j++) wreg[j] = w4[tid + j * NTH];
                }
            }

            // 4 k-steps of m16n8k8 tf32 mma
            #pragma unroll
            for (int ks = 0; ks < 4; ks++) {
                int kc = kt * KT + ks * 8;
                float a[2][4];
                #pragma unroll
                for (int mi = 0; mi < 2; mi++) {
                    int rb = wm * 32 + mi * 16;
                    const float* ap  = &Asm[(rb + g) * AS + kc + tg];
                    const float* ap2 = &Asm[(rb + 8 + g) * AS + kc + tg];
                    a[mi][0] = ap[0];  a[mi][2] = ap[4];
                    a[mi][1] = ap2[0]; a[mi][3] = ap2[4];
                }
                float bf[8][2];
                #pragma unroll
                for (int ni = 0; ni < 8; ni++) {
                    int bc = wn * 64 + ni * 8 + g;
                    bf[ni][0] = wb[(ks * 8 + tg)     * WS + bc];
                    bf[ni][1] = wb[(ks * 8 + tg + 4) * WS + bc];
                }
                #pragma unroll
                for (int mi = 0; mi < 2; mi++)
                    #pragma unroll
                    for (int ni = 0; ni < 8; ni++)
                        mma_tf32(acc[mi][ni], a[mi], bf[ni]);
            }
        }
        __syncthreads();   // all mma reads of Asm/Wt complete

        if (gemm == 0) {
            // epilogue 1: aligned = acc + b1 -> Asm cols [256,512) (tf32)
            #pragma unroll
            for (int mi = 0; mi < 2; mi++)
                #pragma unroll
                for (int ni = 0; ni < 8; ni++)
                    #pragma unroll
                    for (int c = 0; c < 4; c++) {
                        int row = wm * 32 + mi * 16 + g + ((c >> 1) << 3);
                        int col = wn * 64 + ni * 8 + tg * 2 + (c & 1);
                        Asm[row * AS + 256 + col] = to_tf32(acc[mi][ni][c] + b1[col]);
                    }
            __syncthreads();
        }
    }

    // epilogue 2: feats = acc + b2 -> F (fp32, reuses Wt region)
    #pragma unroll
    for (int mi = 0; mi < 2; mi++)
        #pragma unroll
        for (int ni = 0; ni < 8; ni++)
            #pragma unroll
            for (int c = 0; c < 4; c++) {
                int row = wm * 32 + mi * 16 + g + ((c >> 1) << 3);
                int col = wn * 64 + ni * 8 + tg * 2 + (c & 1);
                F[row * WS + col] = acc[mi][ni][c] + b2[col];
            }
    __syncthreads();

    // LayerNorm + exact GELU + residual, one warp per row (8 rows per warp)
    #pragma unroll
    for (int rr = 0; rr < 8; rr++) {
        int r = wid * 8 + rr;
        float x[8];
        #pragma unroll
        for (int j = 0; j < 8; j++) x[j] = F[r * WS + lane + j * 32];
        float s = 0.f, q = 0.f;
        #pragma unroll
        for (int j = 0; j < 8; j++) { s += x[j]; q += x[j] * x[j]; }
        #pragma unroll
        for (int o = 16; o; o >>= 1) {
            s += __shfl_xor_sync(0xffffffffu, s, o);
            q += __shfl_xor_sync(0xffffffffu, q, o);
        }
        float mu  = s * (1.0f / HH);
        float var = q * (1.0f / HH) - mu * mu;
        float rs  = rsqrtf(var + 1e-5f);
        int gbase = (row0 + r) * HH;
        #pragma unroll
        for (int j = 0; j < 8; j++) {
            int c = lane + j * 32;
            float v = (x[j] - mu) * rs * gamma[c] + beta[c];
            float gel = 0.5f * v * (1.0f + erff(v * 0.70710678118654752440f));
            out[gbase + c] = ce[gbase + c] + gel;
        }
    }
}

extern "C" void kernel_launch(void* const* d_in, const int* in_sizes, int n_in,
                              void* d_out, int out_size)
{
    const float* ce    = (const float*)d_in[0];
    const void*  ta    = d_in[1];
    const float* dh    = (const float*)d_in[2];
    const float* W1    = (const float*)d_in[3];
    const float* b1    = (const float*)d_in[4];
    const float* W2    = (const float*)d_in[5];
    const float* b2    = (const float*)d_in[6];
    const float* gamma = (const float*)d_in[7];
    const float* beta  = (const float*)d_in[8];
    float* out = (float*)d_out;

    int M = in_sizes[1];          // B*Lc = 131072
    int grid = M / MT;            // 2048 CTAs
    size_t shmem = (size_t)(MT * AS + 2 * KT * WS) * sizeof(float);  // 199,680 B

    cudaFuncSetAttribute(syl_fused_kernel,
                         cudaFuncAttributeMaxDynamicSharedMemorySize, (int)shmem);
    syl_fused_kernel<<<grid, NTH, shmem>>>(ce, ta, dh, W1, b1, W2, b2, gamma, beta, out);
}

// round 4
// speedup vs baseline: 1.1040x; 1.1040x over previous
#include <cuda_runtime.h>
#include <cstdint>

#define HH    256
#define MT    128
#define NTH   256
#define STG   49152           // ring stage: A 16KB + W 32KB
#define AOFF  0
#define WOFF  16384
#define ALOFF 98304           // aligned/feats tile: 128 x 1024B = 128KB
#define CTL   229376
#define SMEM_SZ 229952

__device__ float g_WT[2][256][512];   // W transposed to [n][k], tf32-rna

__device__ __forceinline__ uint32_t s2u(const void* p) {
    uint32_t a;
    asm("{ .reg .u64 t; cvta.to.shared.u64 t, %1; cvt.u32.u64 %0, t; }" : "=r"(a) : "l"(p));
    return a;
}
__device__ __forceinline__ float to_tf32(float x) {
    uint32_t u; asm("cvt.rna.tf32.f32 %0, %1;" : "=r"(u) : "f"(x));
    return __uint_as_float(u);
}
__device__ __forceinline__ uint32_t to_tf32u(float x) {
    uint32_t u; asm("cvt.rna.tf32.f32 %0, %1;" : "=r"(u) : "f"(x));
    return u;
}
__device__ __forceinline__ void cpa16(uint32_t dst, const void* src) {
    asm volatile("cp.async.cg.shared.global [%0], [%1], 16;" :: "r"(dst), "l"(src));
}
__device__ __forceinline__ void ldsm4(uint32_t* r, uint32_t addr) {
    asm volatile("ldmatrix.sync.aligned.m8n8.x4.shared.b16 {%0,%1,%2,%3}, [%4];"
        : "=r"(r[0]), "=r"(r[1]), "=r"(r[2]), "=r"(r[3]) : "r"(addr));
}
__device__ __forceinline__ void mma8(float* d, const uint32_t* a, uint32_t b0, uint32_t b1) {
    asm volatile(
        "mma.sync.aligned.m16n8k8.row.col.f32.tf32.tf32.f32 "
        "{%0,%1,%2,%3}, {%4,%5,%6,%7}, {%8,%9}, {%0,%1,%2,%3};"
        : "+f"(d[0]), "+f"(d[1]), "+f"(d[2]), "+f"(d[3])
        : "r"(a[0]), "r"(a[1]), "r"(a[2]), "r"(a[3]), "r"(b0), "r"(b1));
}
__device__ __forceinline__ void sts64(uint32_t addr, uint32_t v0, uint32_t v1) {
    asm volatile("st.shared.v2.b32 [%0], {%1,%2};" :: "r"(addr), "r"(v0), "r"(v1));
}

// ---- prep: W[512][256] -> g_WT[w][256][512] tf32 ----
__global__ void prep_wt(const float* __restrict__ W1, const float* __restrict__ W2) {
    __shared__ float t[32][33];
    int b  = blockIdx.x;            // 2 w x 16 kt x 8 nt
    int w  = b & 1;
    int kt = (b >> 1) & 15;
    int nt = b >> 5;
    const float* W = w ? W2 : W1;
    int tx = threadIdx.x & 31, ty = threadIdx.x >> 5;
    #pragma unroll
    for (int p = 0; p < 4; p++) {
        int k = kt * 32 + ty + p * 8, n = nt * 32 + tx;
        t[ty + p * 8][tx] = W[k * 256 + n];
    }
    __syncthreads();
    #pragma unroll
    for (int p = 0; p < 4; p++) {
        int n = nt * 32 + ty + p * 8, k = kt * 32 + tx;
        g_WT[w][n][k] = to_tf32(t[tx][ty + p * 8]);
    }
}

// ---- staging: one pipeline stage (A chunk + W chunk) via cp.async ----
__device__ __forceinline__ void stage(char* smem, uint32_t sb, int row0, int tid,
                                      const float* ce, const float* dh,
                                      const int* sidx, int s)
{
    if (s < 32) {
        const uint32_t base = sb + (uint32_t)(s & 1) * STG;
        // W chunk [256n x 32k], swizzled
        {
            const int w = s >> 4;
            const int koff = (s & 15) * 32;
            const int n = tid >> 1, h = tid & 1;
            #pragma unroll
            for (int p2 = 0; p2 < 2; p2++) {
                int nn = n + 128 * p2;
                const float* src = &g_WT[w][nn][koff + h * 16];
                uint32_t drow = base + WOFF + nn * 128;
                int sw = nn & 7;
                #pragma unroll
                for (int j = 0; j < 4; j++) {
                    int c16 = h * 4 + j;
                    cpa16(drow + ((c16 ^ sw) << 4), src + j * 4);
                }
            }
        }
        // A chunk [128r x 32k] (steps 0-23 only)
        if (s < 24) {
            const int r = tid >> 1, h = tid & 1;
            const uint32_t drow = base + AOFF + r * 128;
            const int sw = r & 7;
            if (s < 8 || s >= 16) {           // char
                const float* src = ce + (size_t)(row0 + r) * HH + (s & 7) * 32 + h * 16;
                #pragma unroll
                for (int j = 0; j < 4; j++) {
                    int c16 = h * 4 + j;
                    cpa16(drow + ((c16 ^ sw) << 4), src + j * 4);
                }
            } else {                           // gather
                int so = sidx[r];
                if (so >= 0) {
                    const float* src = dh + (size_t)so * HH + (s - 8) * 32 + h * 16;
                    #pragma unroll
                    for (int j = 0; j < 4; j++) {
                        int c16 = h * 4 + j;
                        cpa16(drow + ((c16 ^ sw) << 4), src + j * 4);
                    }
                } else {
                    float4 z = make_float4(0.f, 0.f, 0.f, 0.f);
                    #pragma unroll
                    for (int j = 0; j < 4; j++) {
                        int c16 = h * 4 + j;
                        *(float4*)(smem + (size_t)(s & 1) * STG + AOFF + r * 128
                                   + ((c16 ^ sw) << 4)) = z;
                    }
                }
            }
        }
    }
    asm volatile("cp.async.commit_group;" ::: "memory");
}

__global__ __launch_bounds__(NTH, 1)
void syl_k(const float* __restrict__ ce, const void* __restrict__ ta,
           const float* __restrict__ dh,
           const float* __restrict__ b1v, const float* __restrict__ b2v,
           const float* __restrict__ gam, const float* __restrict__ bet,
           float* __restrict__ out)
{
    extern __shared__ char smem[];
    const uint32_t sb = s2u(smem);
    const int tid = threadIdx.x, lane = tid & 31, wid = tid >> 5;
    const int wm = wid >> 2, wn = wid & 3;
    const int g = lane >> 2, tg = lane & 3;
    const int row0 = blockIdx.x * MT;
    int* sidx = (int*)(smem + CTL);
    int* sis  = (int*)(smem + CTL + 512);

    // dtype sniff (int32 vs int64 token_alignment)
    if (wid == 0) {
        const int2* p = (const int2*)ta;
        int2 v = p[lane];
        int ok = (v.y == 0 && v.x >= 0) || (v.y == -1 && v.x < 0);
        ok = __all_sync(0xffffffffu, ok);
        if (lane == 0) *sis = ok;
    }
    __syncthreads();
    if (tid < MT) {
        int gr = row0 + tid;
        long long idx = (*sis) ? ((const long long*)ta)[gr]
                               : (long long)((const int*)ta)[gr];
        int so = -1;
        if (idx >= 0) { int ii = (int)idx; if (ii > 2047) ii = 2047; so = (gr >> 14) * 2048 + ii; }
        sidx[tid] = so;
    }
    __syncthreads();

    // per-thread LDSM geometry
    const int t7   = lane & 7;
    const int rowA = ((lane & 8) ? 8 : 0) + t7;     // A: q1/q3 -> +8 rows
    const int hiA  = (lane & 16) ? 1 : 0;           // A: q2/q3 -> +16B col
    const int rowB = ((lane & 16) ? 8 : 0) + t7;    // B: q2/q3 -> +8 rows
    const int hiB  = (lane & 8) ? 1 : 0;            // B: q1/q3 -> +16B col
    uint32_t aStg[4], aAl[4], bOff[4];
    #pragma unroll
    for (int mi = 0; mi < 4; mi++) {
        aStg[mi] = (uint32_t)(wm * 64 + mi * 16 + rowA) * 128;
        aAl[mi]  = (uint32_t)(wm * 64 + mi * 16 + rowA) * 1024;
    }
    #pragma unroll
    for (int p = 0; p < 4; p++)
        bOff[p] = (uint32_t)(wn * 64 + p * 16 + rowB) * 128;

    float acc[4][8][4];
    #pragma unroll
    for (int mi = 0; mi < 4; mi++)
        #pragma unroll
        for (int ni = 0; ni < 8; ni++)
            #pragma unroll
            for (int c = 0; c < 4; c++) acc[mi][ni][c] = 0.f;

    stage(smem, sb, row0, tid, ce, dh, sidx, 0);
    stage(smem, sb, row0, tid, ce, dh, sidx, 1);

    #pragma unroll 1
    for (int s = 0; s < 32; s++) {
        asm volatile("cp.async.wait_group 1;" ::: "memory");
        __syncthreads();

        // ---- compute(s): 4 k-steps of m64n64 per warp ----
        {
            const uint32_t wbase = sb + (uint32_t)(s & 1) * STG + WOFF;
            const uint32_t abase = sb + (uint32_t)(s & 1) * STG + AOFF;
            #pragma unroll
            for (int ks = 0; ks < 4; ks++) {
                uint32_t a[4][4], b[4][4];
                if (s < 24) {
                    uint32_t swa = (uint32_t)(((ks * 2 + hiA) ^ t7) << 4);
                    #pragma unroll
                    for (int mi = 0; mi < 4; mi++) ldsm4(a[mi], abase + aStg[mi] + swa);
                } else {
                    uint32_t swa = (uint32_t)((((s - 24) * 8 + ks * 2 + hiA) ^ t7) << 4);
                    #pragma unroll
                    for (int mi = 0; mi < 4; mi++) ldsm4(a[mi], sb + ALOFF + aAl[mi] + swa);
                }
                uint32_t swb = (uint32_t)(((ks * 2 + hiB) ^ t7) << 4);
                #pragma unroll
                for (int p = 0; p < 4; p++) ldsm4(b[p], wbase + bOff[p] + swb);
                #pragma unroll
                for (int mi = 0; mi < 4; mi++)
                    #pragma unroll
                    for (int ni = 0; ni < 8; ni++)
                        mma8(acc[mi][ni], a[mi],
                             b[ni >> 1][(ni & 1) * 2], b[ni >> 1][(ni & 1) * 2 + 1]);
            }
        }
        __syncthreads();

        stage(smem, sb, row0, tid, ce, dh, sidx, s + 2);

        if (s == 15) {
            // epilogue 1: aligned = acc + b1 -> swizzled tile (tf32)
            #pragma unroll
            for (int mi = 0; mi < 4; mi++)
                #pragma unroll
                for (int ni = 0; ni < 8; ni++) {
                    int col = wn * 64 + ni * 8 + tg * 2;
                    float2 bb = *(const float2*)(b1v + col);
                    #pragma unroll
                    for (int cp = 0; cp < 2; cp++) {
                        int row = wm * 64 + mi * 16 + g + 8 * cp;
                        uint32_t addr = sb + ALOFF + row * 1024
                                      + (((col >> 2) ^ (row & 7)) << 4) + (col & 3) * 4;
                        sts64(addr,
                              to_tf32u(acc[mi][ni][2 * cp]     + bb.x),
                              to_tf32u(acc[mi][ni][2 * cp + 1] + bb.y));
                    }
                }
            #pragma unroll
            for (int mi = 0; mi < 4; mi++)
                #pragma unroll
                for (int ni = 0; ni < 8; ni++)
                    #pragma unroll
                    for (int c = 0; c < 4; c++) acc[mi][ni][c] = 0.f;
        }
    }

    // ---- epilogue 2: feats = acc + b2 -> plain tile (overlays aligned) ----
    #pragma unroll
    for (int mi = 0; mi < 4; mi++)
        #pragma unroll
        for (int ni = 0; ni < 8; ni++) {
            int col = wn * 64 + ni * 8 + tg * 2;
            float2 bb = *(const float2*)(b2v + col);
            #pragma unroll
            for (int cp = 0; cp < 2; cp++) {
                int row = wm * 64 + mi * 16 + g + 8 * cp;
                uint32_t addr = sb + ALOFF + row * 1024 + col * 4;
                sts64(addr,
                      __float_as_uint(acc[mi][ni][2 * cp]     + bb.x),
                      __float_as_uint(acc[mi][ni][2 * cp + 1] + bb.y));
            }
        }
    __syncthreads();

    // ---- LayerNorm + exact GELU + residual (warp per row, 16 rows/warp) ----
    float* F = (float*)(smem + ALOFF);
    #pragma unroll 1
    for (int rr = 0; rr < 16; rr++) {
        int r = wid * 16 + rr;
        const float* Frow = F + r * 256;
        float x[8];
        float sm = 0.f, q = 0.f;
        #pragma unroll
        for (int j = 0; j < 8; j++) {
            x[j] = Frow[lane + 32 * j];
            sm += x[j]; q += x[j] * x[j];
        }
        #pragma unroll
        for (int o = 16; o; o >>= 1) {
            sm += __shfl_xor_sync(0xffffffffu, sm, o);
            q  += __shfl_xor_sync(0xffffffffu, q, o);
        }
        float mu  = sm * (1.0f / HH);
        float var = q * (1.0f / HH) - mu * mu;
        float rs  = rsqrtf(var + 1e-5f);
        size_t gb = (size_t)(row0 + r) * HH;
        #pragma unroll
        for (int j = 0; j < 8; j++) {
            int cc = lane + 32 * j;
            float v = (x[j] - mu) * rs * __ldg(gam + cc) + __ldg(bet + cc);
            float gel = 0.5f * v * (1.0f + erff(v * 0.70710678118654752440f));
            out[gb + cc] = ce[gb + cc] + gel;
        }
    }
}

extern "C" void kernel_launch(void* const* d_in, const int* in_sizes, int n_in,
                              void* d_out, int out_size)
{
    const float* ce    = (const float*)d_in[0];
    const void*  ta    = d_in[1];
    const float* dh    = (const float*)d_in[2];
    const float* W1    = (const float*)d_in[3];
    const float* b1    = (const float*)d_in[4];
    const float* W2    = (const float*)d_in[5];
    const float* b2    = (const float*)d_in[6];
    const float* gamma = (const float*)d_in[7];
    const float* beta  = (const float*)d_in[8];
    float* out = (float*)d_out;

    int M = in_sizes[0] / HH;     // 131072 rows
    int grid = M / MT;            // 1024 CTAs

    prep_wt<<<256, 256>>>(W1, W2);

    cudaFuncSetAttribute(syl_k, cudaFuncAttributeMaxDynamicSharedMemorySize, SMEM_SZ);
    syl_k<<<grid, NTH, SMEM_SZ>>>(ce, ta, dh, b1, b2, gamma, beta, out);
}

// round 5
// speedup vs baseline: 1.1970x; 1.0843x over previous
#include <cuda_runtime.h>
#include <cstdint>

#define HH    256
#define MT    128
#define NTH   512
#define STG4  24576          // ring stage: A 8KB + W 16KB
#define WOFS  8192
#define ALOFF 98304          // aligned/feats tile: 128 x 1024B
#define CTL   229376
#define SMEM_SZ 229952

__device__ float g_WT[2][256][512];   // W transposed to [n][k], tf32-rna

__device__ __forceinline__ uint32_t s2u(const void* p) {
    uint32_t a;
    asm("{ .reg .u64 t; cvta.to.shared.u64 t, %1; cvt.u32.u64 %0, t; }" : "=r"(a) : "l"(p));
    return a;
}
__device__ __forceinline__ float to_tf32(float x) {
    uint32_t u; asm("cvt.rna.tf32.f32 %0, %1;" : "=r"(u) : "f"(x));
    return __uint_as_float(u);
}
__device__ __forceinline__ uint32_t to_tf32u(float x) {
    uint32_t u; asm("cvt.rna.tf32.f32 %0, %1;" : "=r"(u) : "f"(x));
    return u;
}
__device__ __forceinline__ void cpa16(uint32_t dst, const void* src) {
    asm volatile("cp.async.cg.shared.global [%0], [%1], 16;" :: "r"(dst), "l"(src));
}
__device__ __forceinline__ void ldsm4(uint32_t* r, uint32_t addr) {
    asm volatile("ldmatrix.sync.aligned.m8n8.x4.shared.b16 {%0,%1,%2,%3}, [%4];"
        : "=r"(r[0]), "=r"(r[1]), "=r"(r[2]), "=r"(r[3]) : "r"(addr));
}
__device__ __forceinline__ void mma8(float* d, const uint32_t* a, uint32_t b0, uint32_t b1) {
    asm volatile(
        "mma.sync.aligned.m16n8k8.row.col.f32.tf32.tf32.f32 "
        "{%0,%1,%2,%3}, {%4,%5,%6,%7}, {%8,%9}, {%0,%1,%2,%3};"
        : "+f"(d[0]), "+f"(d[1]), "+f"(d[2]), "+f"(d[3])
        : "r"(a[0]), "r"(a[1]), "r"(a[2]), "r"(a[3]), "r"(b0), "r"(b1));
}
__device__ __forceinline__ void sts64(uint32_t addr, uint32_t v0, uint32_t v1) {
    asm volatile("st.shared.v2.b32 [%0], {%1,%2};" :: "r"(addr), "r"(v0), "r"(v1));
}

// ---- prep: W[512][256] -> g_WT[w][256][512] tf32 ----
__global__ void prep_wt(const float* __restrict__ W1, const float* __restrict__ W2) {
    __shared__ float t[32][33];
    int b  = blockIdx.x;            // 2 w x 16 kt x 8 nt
    int w  = b & 1;
    int kt = (b >> 1) & 15;
    int nt = b >> 5;
    const float* W = w ? W2 : W1;
    int tx = threadIdx.x & 31, ty = threadIdx.x >> 5;
    #pragma unroll
    for (int p = 0; p < 4; p++) {
        int k = kt * 32 + ty + p * 8, n = nt * 32 + tx;
        t[ty + p * 8][tx] = W[k * 256 + n];
    }
    __syncthreads();
    #pragma unroll
    for (int p = 0; p < 4; p++) {
        int n = nt * 32 + ty + p * 8, k = kt * 32 + tx;
        g_WT[w][n][k] = to_tf32(t[tx][ty + p * 8]);
    }
}

// ---- stage s (0..63): A chunk [128r x 16k] + W chunk [256n x 16k] ----
__device__ __forceinline__ void stage(char* smem, uint32_t sb, int row0, int tid,
                                      const float* ce, const float* dh,
                                      const int* sidx, int s)
{
    if (s < 64) {
        const int p0 = s >> 4;
        const int kq = (s & 15) * 16;
        const uint32_t base = sb + (uint32_t)(s & 3) * STG4;
        // W chunk
        {
            const int w  = (p0 >= 2);
            const int wk = kq + ((p0 & 1) ? 256 : 0);
            #pragma unroll
            for (int j = 0; j < 2; j++) {
                int gi = tid * 2 + j;
                int n = gi >> 2, c = gi & 3;
                cpa16(base + WOFS + n * 64 + ((c ^ ((n >> 1) & 3)) << 4),
                      &g_WT[w][n][wk + c * 4]);
            }
        }
        // A chunk (phases 0-2 only)
        if (p0 < 3) {
            const int r = tid >> 2, c = tid & 3;
            const uint32_t off = r * 64 + ((c ^ ((r >> 1) & 3)) << 4);
            if (p0 == 1) {
                int so = sidx[r];
                if (so >= 0) cpa16(base + off, dh + (size_t)so * HH + kq + c * 4);
                else *(float4*)(smem + (size_t)(s & 3) * STG4 + off)
                        = make_float4(0.f, 0.f, 0.f, 0.f);
            } else {
                cpa16(base + off, ce + (size_t)(row0 + r) * HH + kq + c * 4);
            }
        }
    }
    asm volatile("cp.async.commit_group;" ::: "memory");
}

__global__ __launch_bounds__(NTH, 1)
void syl_k(const float* __restrict__ ce, const void* __restrict__ ta,
           const float* __restrict__ dh,
           const float* __restrict__ b1v, const float* __restrict__ b2v,
           const float* __restrict__ gam, const float* __restrict__ bet,
           float* __restrict__ out)
{
    extern __shared__ char smem[];
    const uint32_t sb = s2u(smem);
    const int tid = threadIdx.x, lane = tid & 31, wid = tid >> 5;
    const int wm = wid >> 2, wn = wid & 3;           // 4m x 4n warp grid
    const int g = lane >> 2, tg = lane & 3;
    const int row0 = blockIdx.x * MT;
    int* sidx = (int*)(smem + CTL);
    int* sis  = (int*)(smem + CTL + 512);

    // dtype sniff (int32 vs int64 token_alignment)
    if (wid == 0) {
        const int2* p = (const int2*)ta;
        int2 v = p[lane];
        int ok = (v.y == 0 && v.x >= 0) || (v.y == -1 && v.x < 0);
        ok = __all_sync(0xffffffffu, ok);
        if (lane == 0) *sis = ok;
    }
    __syncthreads();
    if (tid < MT) {
        int gr = row0 + tid;
        long long idx = (*sis) ? ((const long long*)ta)[gr]
                               : (long long)((const int*)ta)[gr];
        int so = -1;
        if (idx >= 0) { int ii = (int)idx; if (ii > 2047) ii = 2047; so = (gr >> 14) * 2048 + ii; }
        sidx[tid] = so;
    }
    __syncthreads();

    // LDSM geometry (identical fragment mapping to validated R4)
    const int t7   = lane & 7;
    const int rowA = ((lane & 8) ? 8 : 0) + t7;
    const int hiA  = (lane & 16) ? 1 : 0;
    const int rowB = ((lane & 16) ? 8 : 0) + t7;
    const int hiB  = (lane & 8) ? 1 : 0;
    const int f4   = (lane >> 1) & 3;                // swizzle fn for 64B rows
    uint32_t aStg[2], aAl[2], bOff[4];
    #pragma unroll
    for (int mi = 0; mi < 2; mi++) {
        aStg[mi] = (uint32_t)(wm * 32 + mi * 16 + rowA) * 64;
        aAl[mi]  = (uint32_t)(wm * 32 + mi * 16 + rowA) * 1024;
    }
    #pragma unroll
    for (int p = 0; p < 4; p++)
        bOff[p] = (uint32_t)(wn * 64 + p * 16 + rowB) * 64;

    float acc[2][8][4];
    #pragma unroll
    for (int mi = 0; mi < 2; mi++)
        #pragma unroll
        for (int ni = 0; ni < 8; ni++)
            #pragma unroll
            for (int c = 0; c < 4; c++) acc[mi][ni][c] = 0.f;

    stage(smem, sb, row0, tid, ce, dh, sidx, 0);
    stage(smem, sb, row0, tid, ce, dh, sidx, 1);
    stage(smem, sb, row0, tid, ce, dh, sidx, 2);

    #pragma unroll 1
    for (int s = 0; s < 64; s++) {
        asm volatile("cp.async.wait_group 2;" ::: "memory");
        __syncthreads();

        stage(smem, sb, row0, tid, ce, dh, sidx, s + 3);

        // ---- compute(s): 2 k-steps of m32n64 per warp ----
        {
            const uint32_t base  = sb + (uint32_t)(s & 3) * STG4;
            const uint32_t wbase = base + WOFS;
            #pragma unroll
            for (int ks = 0; ks < 2; ks++) {
                uint32_t a[2][4], b[4][4];
                if (s < 48) {
                    uint32_t swa = (uint32_t)(((ks * 2 + hiA) ^ f4) << 4);
                    #pragma unroll
                    for (int mi = 0; mi < 2; mi++) ldsm4(a[mi], base + aStg[mi] + swa);
                } else {
                    uint32_t swa = (uint32_t)((((s - 48) * 4 + ks * 2 + hiA) ^ t7) << 4);
                    #pragma unroll
                    for (int mi = 0; mi < 2; mi++) ldsm4(a[mi], sb + ALOFF + aAl[mi] + swa);
                }
                uint32_t swb = (uint32_t)(((ks * 2 + hiB) ^ f4) << 4);
                #pragma unroll
                for (int p = 0; p < 4; p++) ldsm4(b[p], wbase + bOff[p] + swb);
                #pragma unroll
                for (int mi = 0; mi < 2; mi++)
                    #pragma unroll
                    for (int ni = 0; ni < 8; ni++)
                        mma8(acc[mi][ni], a[mi],
                             b[ni >> 1][(ni & 1) * 2], b[ni >> 1][(ni & 1) * 2 + 1]);
            }
        }

        if (s == 31) {
            // epilogue 1: aligned = acc + b1 -> swizzled tile (tf32)
            #pragma unroll
            for (int mi = 0; mi < 2; mi++)
                #pragma unroll
                for (int ni = 0; ni < 8; ni++) {
                    int col = wn * 64 + ni * 8 + tg * 2;
                    float2 bb = *(const float2*)(b1v + col);
                    #pragma unroll
                    for (int cp = 0; cp < 2; cp++) {
                        int row = wm * 32 + mi * 16 + g + 8 * cp;
                        uint32_t addr = sb + ALOFF + row * 1024
                                      + (((col >> 2) ^ (row & 7)) << 4) + (col & 3) * 4;
                        sts64(addr,
                              to_tf32u(acc[mi][ni][2 * cp]     + bb.x),
                              to_tf32u(acc[mi][ni][2 * cp + 1] + bb.y));
                    }
                }
            #pragma unroll
            for (int mi = 0; mi < 2; mi++)
                #pragma unroll
                for (int ni = 0; ni < 8; ni++)
                    #pragma unroll
                    for (int c = 0; c < 4; c++) acc[mi][ni][c] = 0.f;
        }
    }
    __syncthreads();   // all LDSM reads of aligned tile done before feats overlay

    // ---- epilogue 2: feats = acc + b2 -> plain tile ----
    #pragma unroll
    for (int mi = 0; mi < 2; mi++)
        #pragma unroll
        for (int ni = 0; ni < 8; ni++) {
            int col = wn * 64 + ni * 8 + tg * 2;
            float2 bb = *(const float2*)(b2v + col);
            #pragma unroll
            for (int cp = 0; cp < 2; cp++) {
                int row = wm * 32 + mi * 16 + g + 8 * cp;
                uint32_t addr = sb + ALOFF + row * 1024 + col * 4;
                sts64(addr,
                      __float_as_uint(acc[mi][ni][2 * cp]     + bb.x),
                      __float_as_uint(acc[mi][ni][2 * cp + 1] + bb.y));
            }
        }
    __syncthreads();

    // ---- LayerNorm + exact GELU + residual (warp per row, 8 rows/warp) ----
    float* F = (float*)(smem + ALOFF);
    #pragma unroll 1
    for (int rr = 0; rr < 8; rr++) {
        int r = wid * 8 + rr;
        const float* Frow = F + r * 256;
        float x[8];
        float sm = 0.f, q = 0.f;
        #pragma unroll
        for (int j = 0; j < 8; j++) {
            x[j] = Frow[lane + 32 * j];
            sm += x[j]; q += x[j] * x[j];
        }
        #pragma unroll
        for (int o = 16; o; o >>= 1) {
            sm += __shfl_xor_sync(0xffffffffu, sm, o);
            q  += __shfl_xor_sync(0xffffffffu, q, o);
        }
        float mu  = sm * (1.0f / HH);
        float var = q * (1.0f / HH) - mu * mu;
        float rs  = rsqrtf(var + 1e-5f);
        size_t gb = (size_t)(row0 + r) * HH;
        #pragma unroll
        for (int j = 0; j < 8; j++) {
            int cc = lane + 32 * j;
            float v = (x[j] - mu) * rs * __ldg(gam + cc) + __ldg(bet + cc);
            float gel = 0.5f * v * (1.0f + erff(v * 0.70710678118654752440f));
            out[gb + cc] = ce[gb + cc] + gel;
        }
    }
}

extern "C" void kernel_launch(void* const* d_in, const int* in_sizes, int n_in,
                              void* d_out, int out_size)
{
    const float* ce    = (const float*)d_in[0];
    const void*  ta    = d_in[1];
    const float* dh    = (const float*)d_in[2];
    const float* W1    = (const float*)d_in[3];
    const float* b1    = (const float*)d_in[4];
    const float* W2    = (const float*)d_in[5];
    const float* b2    = (const float*)d_in[6];
    const float* gamma = (const float*)d_in[7];
    const float* beta  = (const float*)d_in[8];
    float* out = (float*)d_out;

    int M = in_sizes[0] / HH;     // 131072 rows
    int grid = M / MT;            // 1024 CTAs

    prep_wt<<<256, 256>>>(W1, W2);

    cudaFuncSetAttribute(syl_k, cudaFuncAttributeMaxDynamicSharedMemorySize, SMEM_SZ);
    syl_k<<<grid, NTH, SMEM_SZ>>>(ce, ta, dh, b1, b2, gamma, beta, out);
}

// round 7
// speedup vs baseline: 1.9135x; 1.5985x over previous
#include <cuda_runtime.h>
#include <cuda_fp16.h>
#include <cstdint>

#define HH    256
#define MT    128
#define NTH   512
#define STG4  24576          // ring stage: A 8KB(fp16) + W 16KB(fp16)
#define WOFS  8192
#define ALOFF 98304          // aligned tile fp16: 128 x 512B = 64KB
#define CTL   163840
#define SMEM_SZ 164864

__device__ __half g_ce[33554432];      // ce fp16 [131072][256]
__device__ __half g_dh[4194304];       // dh fp16 [16384][256]
__device__ __half g_WT[2][256][512];   // W transposed [n][k] fp16

__device__ __forceinline__ uint32_t h2u(__half2 h) {
    return *reinterpret_cast<uint32_t*>(&h);
}
__device__ __forceinline__ uint32_t s2u(const void* p) {
    uint32_t a;
    asm("{ .reg .u64 t; cvta.to.shared.u64 t, %1; cvt.u32.u64 %0, t; }" : "=r"(a) : "l"(p));
    return a;
}
__device__ __forceinline__ void cpa16(uint32_t dst, const void* src) {
    asm volatile("cp.async.cg.shared.global [%0], [%1], 16;" :: "r"(dst), "l"(src));
}
__device__ __forceinline__ void ldsm4(uint32_t* r, uint32_t addr) {
    asm volatile("ldmatrix.sync.aligned.m8n8.x4.shared.b16 {%0,%1,%2,%3}, [%4];"
        : "=r"(r[0]), "=r"(r[1]), "=r"(r[2]), "=r"(r[3]) : "r"(addr));
}
__device__ __forceinline__ void mma16(float* d, const uint32_t* a, uint32_t b0, uint32_t b1) {
    asm volatile(
        "mma.sync.aligned.m16n8k16.row.col.f32.f16.f16.f32 "
        "{%0,%1,%2,%3}, {%4,%5,%6,%7}, {%8,%9}, {%0,%1,%2,%3};"
        : "+f"(d[0]), "+f"(d[1]), "+f"(d[2]), "+f"(d[3])
        : "r"(a[0]), "r"(a[1]), "r"(a[2]), "r"(a[3]), "r"(b0), "r"(b1));
}
__device__ __forceinline__ void sts32(uint32_t addr, uint32_t v) {
    asm volatile("st.shared.b32 [%0], %1;" :: "r"(addr), "r"(v));
}
__device__ __forceinline__ void sts64(uint32_t addr, uint32_t v0, uint32_t v1) {
    asm volatile("st.shared.v2.b32 [%0], {%1,%2};" :: "r"(addr), "r"(v0), "r"(v1));
}

// ---- prep: fp32 -> fp16 streaming converts ----
__global__ void prep_f16(const float* __restrict__ src, __half* __restrict__ dst) {
    int i = blockIdx.x * blockDim.x + threadIdx.x;   // 8 floats per thread
    const float4* s4 = (const float4*)src;
    float4 v0 = s4[2 * i], v1 = s4[2 * i + 1];
    __half2 h0 = __floats2half2_rn(v0.x, v0.y);
    __half2 h1 = __floats2half2_rn(v0.z, v0.w);
    __half2 h2 = __floats2half2_rn(v1.x, v1.y);
    __half2 h3 = __floats2half2_rn(v1.z, v1.w);
    uint4 o;
    o.x = h2u(h0); o.y = h2u(h1);
    o.z = h2u(h2); o.w = h2u(h3);
    ((uint4*)dst)[i] = o;
}

// ---- prep: W[512][256] -> g_WT[w][256][512] fp16 ----
__global__ void prep_wt(const float* __restrict__ W1, const float* __restrict__ W2) {
    __shared__ float t[32][33];
    int b  = blockIdx.x;            // 2 w x 16 kt x 8 nt
    int w  = b & 1;
    int kt = (b >> 1) & 15;
    int nt = b >> 5;
    const float* W = w ? W2 : W1;
    int tx = threadIdx.x & 31, ty = threadIdx.x >> 5;
    #pragma unroll
    for (int p = 0; p < 4; p++) {
        int k = kt * 32 + ty + p * 8, n = nt * 32 + tx;
        t[ty + p * 8][tx] = W[k * 256 + n];
    }
    __syncthreads();
    #pragma unroll
    for (int p = 0; p < 4; p++) {
        int n = nt * 32 + ty + p * 8, k = kt * 32 + tx;
        g_WT[w][n][k] = __float2half_rn(t[tx][ty + p * 8]);
    }
}

// ---- stage s (0..31): A chunk [128r x 32k fp16] + W chunk [256n x 32k fp16] ----
__device__ __forceinline__ void stage(char* smem, uint32_t sb, int row0, int tid,
                                      const int* sidx, int s)
{
    if (s < 32) {
        const int p0 = s >> 3;
        const int kq = (s & 7) * 32;                 // halves
        const uint32_t base = sb + (uint32_t)(s & 3) * STG4;
        // W chunk: 1024 x 16B, 2 per thread
        {
            const int w  = (p0 >= 2);
            const int wk = kq + ((p0 & 1) ? 256 : 0);
            #pragma unroll
            for (int j = 0; j < 2; j++) {
                int gi = tid * 2 + j;
                int n = gi >> 2, c = gi & 3;
                cpa16(base + WOFS + n * 64 + ((c ^ ((n >> 1) & 3)) << 4),
                      &g_WT[w][n][wk + c * 8]);
            }
        }
        // A chunk: 512 x 16B, 1 per thread (phases 0-2)
        if (p0 < 3) {
            const int r = tid >> 2, c = tid & 3;
            const uint32_t off = r * 64 + ((c ^ ((r >> 1) & 3)) << 4);
            if (p0 == 1) {
                int so = sidx[r];
                if (so >= 0) cpa16(base + off, g_dh + (size_t)so * HH + kq + c * 8);
                else *(float4*)(smem + (size_t)(s & 3) * STG4 + off)
                        = make_float4(0.f, 0.f, 0.f, 0.f);
            } else {
                cpa16(base + off, g_ce + (size_t)(row0 + r) * HH + kq + c * 8);
            }
        }
    }
    asm volatile("cp.async.commit_group;" ::: "memory");
}

__global__ __launch_bounds__(NTH, 1)
void syl_k(const float* __restrict__ ce, const void* __restrict__ ta,
           const float* __restrict__ b1v, const float* __restrict__ b2v,
           const float* __restrict__ gam, const float* __restrict__ bet,
           float* __restrict__ out)
{
    extern __shared__ char smem[];
    const uint32_t sb = s2u(smem);
    const int tid = threadIdx.x, lane = tid & 31, wid = tid >> 5;
    const int wm = wid >> 2, wn = wid & 3;           // 4m x 4n warp grid
    const int g = lane >> 2, tg = lane & 3;
    const int row0 = blockIdx.x * MT;
    int* sidx = (int*)(smem + CTL);
    int* sis  = (int*)(smem + CTL + 512);

    // dtype sniff (int32 vs int64 token_alignment)
    if (wid == 0) {
        const int2* p = (const int2*)ta;
        int2 v = p[lane];
        int ok = (v.y == 0 && v.x >= 0) || (v.y == -1 && v.x < 0);
        ok = __all_sync(0xffffffffu, ok);
        if (lane == 0) *sis = ok;
    }
    __syncthreads();
    if (tid < MT) {
        int gr = row0 + tid;
        long long idx = (*sis) ? ((const long long*)ta)[gr]
                               : (long long)((const int*)ta)[gr];
        int so = -1;
        if (idx >= 0) { int ii = (int)idx; if (ii > 2047) ii = 2047; so = (gr >> 14) * 2048 + ii; }
        sidx[tid] = so;
    }
    __syncthreads();

    // LDSM geometry (identical to validated tf32 mapping)
    const int t7   = lane & 7;
    const int rowA = ((lane & 8) ? 8 : 0) + t7;
    const int hiA  = (lane & 16) ? 1 : 0;
    const int rowB = ((lane & 16) ? 8 : 0) + t7;
    const int hiB  = (lane & 8) ? 1 : 0;
    const int f4   = (lane >> 1) & 3;                // swizzle fn for 64B rows
    uint32_t aStg[2], aAl[2], bOff[4];
    #pragma unroll
    for (int mi = 0; mi < 2; mi++) {
        aStg[mi] = (uint32_t)(wm * 32 + mi * 16 + rowA) * 64;
        aAl[mi]  = (uint32_t)(wm * 32 + mi * 16 + rowA) * 512;
    }
    #pragma unroll
    for (int p = 0; p < 4; p++)
        bOff[p] = (uint32_t)(wn * 64 + p * 16 + rowB) * 64;

    float acc[2][8][4];
    #pragma unroll
    for (int mi = 0; mi < 2; mi++)
        #pragma unroll
        for (int ni = 0; ni < 8; ni++)
            #pragma unroll
            for (int c = 0; c < 4; c++) acc[mi][ni][c] = 0.f;

    stage(smem, sb, row0, tid, sidx, 0);
    stage(smem, sb, row0, tid, sidx, 1);
    stage(smem, sb, row0, tid, sidx, 2);

    #pragma unroll 1
    for (int s = 0; s < 32; s++) {
        asm volatile("cp.async.wait_group 2;" ::: "memory");
        __syncthreads();

        stage(smem, sb, row0, tid, sidx, s + 3);

        // ---- compute(s): 2 k16-steps of m32n64 per warp ----
        {
            const uint32_t base  = sb + (uint32_t)(s & 3) * STG4;
            const uint32_t wbase = base + WOFS;
            #pragma unroll
            for (int ks = 0; ks < 2; ks++) {
                uint32_t a[2][4], b[4][4];
                if (s < 24) {
                    uint32_t swa = (uint32_t)(((ks * 2 + hiA) ^ f4) << 4);
                    #pragma unroll
                    for (int mi = 0; mi < 2; mi++) ldsm4(a[mi], base + aStg[mi] + swa);
                } else {
                    uint32_t kk = (uint32_t)((s - 24) * 4 + ks * 2 + hiA);
                    uint32_t swa = (uint32_t)((kk ^ (uint32_t)t7) << 4);
                    #pragma unroll
                    for (int mi = 0; mi < 2; mi++) ldsm4(a[mi], sb + ALOFF + aAl[mi] + swa);
                }
                uint32_t swb = (uint32_t)(((ks * 2 + hiB) ^ f4) << 4);
                #pragma unroll
                for (int p = 0; p < 4; p++) ldsm4(b[p], wbase + bOff[p] + swb);
                #pragma unroll
                for (int mi = 0; mi < 2; mi++)
                    #pragma unroll
                    for (int ni = 0; ni < 8; ni++)
                        mma16(acc[mi][ni], a[mi],
                              b[ni >> 1][(ni & 1) * 2], b[ni >> 1][(ni & 1) * 2 + 1]);
            }
        }

        if (s == 15) {
            // epilogue 1: aligned = fp16(acc + b1) -> swizzled tile (512B rows)
            #pragma unroll
            for (int mi = 0; mi < 2; mi++)
                #pragma unroll
                for (int ni = 0; ni < 8; ni++) {
                    int col = wn * 64 + ni * 8 + tg * 2;
                    float2 bb = *(const float2*)(b1v + col);
                    #pragma unroll
                    for (int cp = 0; cp < 2; cp++) {
                        int row = wm * 32 + mi * 16 + g + 8 * cp;
                        __half2 h = __floats2half2_rn(acc[mi][ni][2 * cp]     + bb.x,
                                                      acc[mi][ni][2 * cp + 1] + bb.y);
                        uint32_t addr = sb + ALOFF + row * 512
                                      + ((((col >> 3) ^ (row & 7)) << 4) | ((col & 7) * 2));
                        sts32(addr, h2u(h));
                    }
                }
            #pragma unroll
            for (int mi = 0; mi < 2; mi++)
                #pragma unroll
                for (int ni = 0; ni < 8; ni++)
                    #pragma unroll
                    for (int c = 0; c < 4; c++) acc[mi][ni][c] = 0.f;
        }
    }
    __syncthreads();   // all LDSM reads of aligned tile done

    // ---- epilogue 2: feats(fp32) = acc + b2 -> smem offset 0, stride 256 ----
    #pragma unroll
    for (int mi = 0; mi < 2; mi++)
        #pragma unroll
        for (int ni = 0; ni < 8; ni++) {
            int col = wn * 64 + ni * 8 + tg * 2;
            float2 bb = *(const float2*)(b2v + col);
            #pragma unroll
            for (int cp = 0; cp < 2; cp++) {
                int row = wm * 32 + mi * 16 + g + 8 * cp;
                uint32_t addr = sb + row * 1024 + col * 4;
                sts64(addr,
                      __float_as_uint(acc[mi][ni][2 * cp]     + bb.x),
                      __float_as_uint(acc[mi][ni][2 * cp + 1] + bb.y));
            }
        }
    __syncthreads();

    // ---- LayerNorm + exact GELU + residual (warp per row, 8 rows/warp) ----
    float* F = (float*)smem;
    #pragma unroll 1
    for (int rr = 0; rr < 8; rr++) {
        int r = wid * 8 + rr;
        const float* Frow = F + r * 256;
        float x[8];
        float sm = 0.f, q = 0.f;
        #pragma unroll
        for (int j = 0; j < 8; j++) {
            x[j] = Frow[lane + 32 * j];
            sm += x[j]; q += x[j] * x[j];
        }
        #pragma unroll
        for (int o = 16; o; o >>= 1) {
            sm += __shfl_xor_sync(0xffffffffu, sm, o);
            q  += __shfl_xor_sync(0xffffffffu, q, o);
        }
        float mu  = sm * (1.0f / HH);
        float var = q * (1.0f / HH) - mu * mu;
        float rs  = rsqrtf(var + 1e-5f);
        size_t gb = (size_t)(row0 + r) * HH;
        #pragma unroll
        for (int j = 0; j < 8; j++) {
            int cc = lane + 32 * j;
            float v = (x[j] - mu) * rs * __ldg(gam + cc) + __ldg(bet + cc);
            float gel = 0.5f * v * (1.0f + erff(v * 0.70710678118654752440f));
            out[gb + cc] = ce[gb + cc] + gel;
        }
    }
}

extern "C" void kernel_launch(void* const* d_in, const int* in_sizes, int n_in,
                              void* d_out, int out_size)
{
    const float* ce    = (const float*)d_in[0];
    const void*  ta    = d_in[1];
    const float* dh    = (const float*)d_in[2];
    const float* W1    = (const float*)d_in[3];
    const float* b1    = (const float*)d_in[4];
    const float* W2    = (const float*)d_in[5];
    const float* b2    = (const float*)d_in[6];
    const float* gamma = (const float*)d_in[7];
    const float* beta  = (const float*)d_in[8];
    float* out = (float*)d_out;

    int M = in_sizes[0] / HH;     // 131072 rows
    int grid = M / MT;            // 1024 CTAs

    __half *d_ce16, *d_dh16;
    cudaGetSymbolAddress((void**)&d_ce16, g_ce);
    cudaGetSymbolAddress((void**)&d_dh16, g_dh);

    prep_f16<<<(M * HH / 8 + 511) / 512, 512>>>(ce, d_ce16);
    prep_f16<<<(in_sizes[2] / 8 + 511) / 512, 512>>>(dh, d_dh16);
    prep_wt<<<256, 256>>>(W1, W2);

    cudaFuncSetAttribute(syl_k, cudaFuncAttributeMaxDynamicSharedMemorySize, SMEM_SZ);
    syl_k<<<grid, NTH, SMEM_SZ>>>(ce, ta, b1, b2, gamma, beta, out);
}